// round 11
// baseline (speedup 1.0000x reference)
#include <cuda_runtime.h>
#include <cuda_fp16.h>

#define HIDDEN 768
#define HEAD 64
#define BATCH 4
#define SEQL 4096
#define MTOT (BATCH*SEQL)

typedef unsigned long long u64;
typedef unsigned int u32;
typedef unsigned short u16;

// scratch — __device__ globals, no allocation
__device__ __align__(256) u16 g_qh[MTOT*HEAD];
__device__ __align__(256) u16 g_kh[MTOT*HEAD];
__device__ __align__(256) u16 g_vh[MTOT*HEAD];
__device__ __align__(256) u16 g_wh[3*HIDDEN*HEAD];
__device__ __align__(256) u16 g_wo_hi[HEAD*HIDDEN];
__device__ __align__(256) u16 g_wo_lo[HEAD*HIDDEN];
__device__ __align__(256) float g_o0[MTOT*HEAD];
__device__ __align__(256) float g_o1[MTOT*HEAD];
__device__ __align__(256) float g_l0[MTOT];
__device__ __align__(256) float g_l1[MTOT];

// ---------------------------------------------------------------------------
// helpers
// ---------------------------------------------------------------------------
__device__ __forceinline__ u32 smem_u32(const void* p){
    u32 a; asm("{ .reg .u64 t; cvta.to.shared.u64 t, %1; cvt.u32.u64 %0, t; }" : "=r"(a) : "l"(p));
    return a;
}
__device__ __forceinline__ void ldsm_x4(u32 &r0, u32 &r1, u32 &r2, u32 &r3, u32 addr){
    asm volatile("ldmatrix.sync.aligned.m8n8.x4.shared.b16 {%0,%1,%2,%3}, [%4];"
        : "=r"(r0), "=r"(r1), "=r"(r2), "=r"(r3) : "r"(addr));
}
__device__ __forceinline__ void ldsm_x4t(u32 &r0, u32 &r1, u32 &r2, u32 &r3, u32 addr){
    asm volatile("ldmatrix.sync.aligned.m8n8.x4.trans.shared.b16 {%0,%1,%2,%3}, [%4];"
        : "=r"(r0), "=r"(r1), "=r"(r2), "=r"(r3) : "r"(addr));
}
__device__ __forceinline__ void mma_f16(float* c, u32 a0, u32 a1, u32 a2, u32 a3, u32 b0, u32 b1){
    asm volatile("mma.sync.aligned.m16n8k16.row.col.f32.f16.f16.f32 "
        "{%0,%1,%2,%3}, {%4,%5,%6,%7}, {%8,%9}, {%0,%1,%2,%3};"
        : "+f"(c[0]), "+f"(c[1]), "+f"(c[2]), "+f"(c[3])
        : "r"(a0), "r"(a1), "r"(a2), "r"(a3), "r"(b0), "r"(b1));
}
__device__ __forceinline__ u32 h2(float a, float b){
    __half2 h = __floats2half2_rn(a, b);
    return *(u32*)&h;
}
__device__ __forceinline__ void h2split(float a, float b, u32 &hi, u32 &lo){
    __half ha = __float2half_rn(a), hb = __float2half_rn(b);
    __half2 hh = __halves2half2(ha, hb);
    hi = *(u32*)&hh;
    __half2 ll = __floats2half2_rn(a - __half2float(ha), b - __half2float(hb));
    lo = *(u32*)&ll;
}
__device__ __forceinline__ void cp16(u32 dst, const void* src){
    asm volatile("cp.async.cg.shared.global [%0], [%1], 16;" :: "r"(dst), "l"(src));
}
#define CP_COMMIT() asm volatile("cp.async.commit_group;" ::: "memory")
#define CP_WAIT0()  asm volatile("cp.async.wait_group 0;" ::: "memory")
#define CP_WAIT1()  asm volatile("cp.async.wait_group 1;" ::: "memory")

// ============================================================================
// Kernel 0: weight pre-convert. Wq/Wk/Wv -> f16; Wo -> f16 hi/lo split.
// ============================================================================
__global__ void wcvt_kernel(const float* __restrict__ Wq,
                            const float* __restrict__ Wk,
                            const float* __restrict__ Wv,
                            const float* __restrict__ Wo)
{
    int slot = blockIdx.x*256 + threadIdx.x;
    if (slot < 73728){
        int w = slot / 24576, rem = slot % 24576;
        const float* W = (w==0)?Wq:((w==1)?Wk:Wv);
        float2 v = *(const float2*)&W[rem*2];
        *(u32*)&g_wh[w*(HIDDEN*HEAD) + rem*2] = h2(v.x, v.y);
    } else {
        int s = slot - 73728;
        float2 v = *(const float2*)&Wo[s*2];
        u32 hi, lo; h2split(v.x, v.y, hi, lo);
        *(u32*)&g_wo_hi[s*2] = hi;
        *(u32*)&g_wo_lo[s*2] = lo;
    }
}

// ============================================================================
// Kernel 1: merged QKV projection (unchanged from R7-R10 pass).
// ============================================================================
#define QKV_P 72
#define QKV_XS0 0
#define QKV_XS1 (128*QKV_P)
#define QKV_WS0 (2*128*QKV_P)
#define QKV_WS1 (QKV_WS0 + 3*64*QKV_P)
#define QKV_SMEM ((2*128*QKV_P + 2*3*64*QKV_P)*2)   // 92160 B

__global__ __launch_bounds__(256) void qkv_hmma(
    const float* __restrict__ x,
    const float* __restrict__ bq,
    const float* __restrict__ bk,
    const float* __restrict__ bv)
{
    extern __shared__ u16 smq[];
    const int tid  = threadIdx.x;
    const int warp = tid >> 5;
    const int lane = tid & 31;
    const int m0 = blockIdx.x * 128;

    const u32 smb = smem_u32(smq);
    const int l15 = lane & 15;
    const int lhi = ((lane >> 4) & 1) * 8;
    const u32 xa[2] = { smb + (QKV_XS0 + (warp*16 + l15)*QKV_P + lhi)*2,
                        smb + (QKV_XS1 + (warp*16 + l15)*QKV_P + lhi)*2 };
    const u32 wb[2] = { smb + (QKV_WS0 + l15*QKV_P + lhi)*2,
                        smb + (QKV_WS1 + l15*QKV_P + lhi)*2 };

    float4 xstage[8];

    auto stage_x = [&](int kk){
        #pragma unroll
        for (int i=0;i<8;i++){
            int slot = tid + i*256;
            int row = slot >> 4, c4 = slot & 15;
            xstage[i] = *(const float4*)&x[(size_t)(m0+row)*HIDDEN + kk + c4*4];
        }
    };
    auto store_x = [&](int buf){
        u32 base = buf ? (u32)QKV_XS1 : (u32)QKV_XS0;
        #pragma unroll
        for (int i=0;i<8;i++){
            int slot = tid + i*256;
            int row = slot >> 4, c4 = slot & 15;
            *(uint2*)&smq[base + row*QKV_P + c4*4] =
                make_uint2(h2(xstage[i].x, xstage[i].y), h2(xstage[i].z, xstage[i].w));
        }
    };
    auto issue_w = [&](int kk, int buf){
        u32 base = smb + (buf ? (u32)QKV_WS1 : (u32)QKV_WS0)*2;
        #pragma unroll
        for (int i=0;i<6;i++){
            int slot = tid + i*256;
            int w = slot >> 9, row = (slot >> 3) & 63, ch = slot & 7;
            u32 dst = base + ((w*64 + row)*QKV_P + ch*8)*2;
            const u16* src = &g_wh[(size_t)w*(HIDDEN*HEAD) + (size_t)(kk+row)*HEAD + ch*8];
            cp16(dst, src);
        }
        CP_COMMIT();
    };

    float acc[3][8][4];
    #pragma unroll
    for (int w=0;w<3;w++)
        #pragma unroll
        for (int i=0;i<8;i++)
            #pragma unroll
            for (int j=0;j<4;j++) acc[w][i][j] = 0.f;

    stage_x(0);
    issue_w(0, 0);
    store_x(0);
    issue_w(64, 1);
    stage_x(64);

    for (int t=0; t<12; t++){
        if (t < 11) CP_WAIT1(); else CP_WAIT0();
        __syncthreads();

        const u32 xab = xa[t&1];
        const u32 wbb = wb[t&1];
        #pragma unroll
        for (int kb=0; kb<4; kb++){
            u32 a0,a1,a2,a3;
            ldsm_x4(a0,a1,a2,a3, xab + kb*32);
            #pragma unroll
            for (int w=0; w<3; w++){
                u32 rowoff = ((u32)(w*64 + kb*16)*QKV_P)*2;
                #pragma unroll
                for (int n16=0; n16<4; n16++){
                    u32 b0,b1,b2,b3;
                    ldsm_x4t(b0,b1,b2,b3, wbb + rowoff + n16*32);
                    mma_f16(acc[w][n16*2  ], a0,a1,a2,a3, b0,b1);
                    mma_f16(acc[w][n16*2+1], a0,a1,a2,a3, b2,b3);
                }
            }
        }

        if (t < 11) store_x((t+1)&1);
        __syncthreads();
        if (t < 10){
            issue_w((t+2)*64, t&1);
            stage_x((t+2)*64);
        }
    }

    const int r = m0 + warp*16 + (lane >> 2);
    const int c = (lane & 3)*2;
    #pragma unroll
    for (int w=0; w<3; w++){
        const float* bias = (w==0)?bq:((w==1)?bk:bv);
        u16* out = (w==0)?g_qh:((w==1)?g_kh:g_vh);
        const float scale = (w==0)?0.125f:1.0f;
        #pragma unroll
        for (int nb=0; nb<8; nb++){
            int n = nb*8 + c;
            float b0v = bias[n], b1v = bias[n+1];
            *(u32*)&out[(size_t)r*HEAD + n] =
                h2((acc[w][nb][0]+b0v)*scale, (acc[w][nb][1]+b1v)*scale);
            *(u32*)&out[(size_t)(r+8)*HEAD + n] =
                h2((acc[w][nb][2]+b0v)*scale, (acc[w][nb][3]+b1v)*scale);
        }
    }
}

// ============================================================================
// Kernel 2: HMMA flash attention (unchanged from R10 pass).
// ============================================================================
#define AP 72
#define A_Q  0
#define A_K0 (128*AP)
#define A_K1 (2*128*AP)
#define A_V0 (3*128*AP)
#define A_V1 (4*128*AP)
#define ATTN_SMEM (5*128*AP*2)   // 92160 B

__global__ __launch_bounds__(256, 2) void attn_hmma_kernel()
{
    extern __shared__ u16 smh[];
    const int tid  = threadIdx.x;
    const int warp = tid >> 5;
    const int lane = tid & 31;
    const int b = blockIdx.y, qt = blockIdx.x, z = blockIdx.z;
    const int t0 = z*16;

    const u16* __restrict__ qg = g_qh + ((size_t)b*SEQL + qt*128)*HEAD;
    const u16* __restrict__ kg = g_kh + (size_t)b*SEQL*HEAD;
    const u16* __restrict__ vg = g_vh + (size_t)b*SEQL*HEAD;

    const u32 smb = smem_u32(smh);
    const int l15 = lane & 15;
    const int lhi = ((lane >> 4) & 1) * 8;
    const u32 qbase = smb + (A_Q + (warp*16 + l15)*AP + lhi)*2;
    const u32 kb_[2] = { smb + (A_K0 + l15*AP + lhi)*2, smb + (A_K1 + l15*AP + lhi)*2 };
    const u32 vb_[2] = { smb + (A_V0 + l15*AP + lhi)*2, smb + (A_V1 + l15*AP + lhi)*2 };

    auto issue_kv = [&](int t, int buf){
        u32 kdst = smb + ((buf ? A_K1 : A_K0))*2;
        u32 vdst = smb + ((buf ? A_V1 : A_V0))*2;
        const u16* ks = kg + (size_t)t*128*HEAD;
        const u16* vs = vg + (size_t)t*128*HEAD;
        #pragma unroll
        for (int i=0;i<4;i++){
            int slot = tid + i*256;
            int row = slot >> 3, ch = slot & 7;
            u32 off = (u32)(row*AP + ch*8)*2;
            cp16(kdst + off, ks + row*HEAD + ch*8);
            cp16(vdst + off, vs + row*HEAD + ch*8);
        }
        CP_COMMIT();
    };

    {
        #pragma unroll
        for (int i=0;i<4;i++){
            int slot = tid + i*256;
            int row = slot >> 3, ch = slot & 7;
            cp16(smb + (A_Q + row*AP + ch*8)*2, qg + row*HEAD + ch*8);
        }
        u32 kdst = smb + A_K0*2, vdst = smb + A_V0*2;
        const u16* ks = kg + (size_t)t0*128*HEAD;
        const u16* vs = vg + (size_t)t0*128*HEAD;
        #pragma unroll
        for (int i=0;i<4;i++){
            int slot = tid + i*256;
            int row = slot >> 3, ch = slot & 7;
            u32 off = (u32)(row*AP + ch*8)*2;
            cp16(kdst + off, ks + row*HEAD + ch*8);
            cp16(vdst + off, vs + row*HEAD + ch*8);
        }
        CP_COMMIT();
        issue_kv(t0+1, 1);
    }

    float oacc[8][4];
    #pragma unroll
    for (int i=0;i<8;i++)
        #pragma unroll
        for (int j=0;j<4;j++) oacc[i][j] = 0.f;
    float lsum0 = 0.f, lsum1 = 0.f;
    u32 qf[4][4];
    bool qloaded = false;

    for (int t = 0; t < 16; t++){
        if (t < 15) CP_WAIT1(); else CP_WAIT0();
        __syncthreads();

        if (!qloaded){
            #pragma unroll
            for (int kb=0; kb<4; kb++)
                ldsm_x4(qf[kb][0], qf[kb][1], qf[kb][2], qf[kb][3], qbase + kb*32);
            qloaded = true;
        }

        const u32 kbb = kb_[t&1];
        const u32 vbb = vb_[t&1];

        #pragma unroll
        for (int h=0; h<4; h++){
            float sacc[4][4];
            #pragma unroll
            for (int i=0;i<4;i++)
                #pragma unroll
                for (int j=0;j<4;j++) sacc[i][j] = 0.f;

            #pragma unroll
            for (int kb=0; kb<4; kb++){
                #pragma unroll
                for (int e=0; e<2; e++){
                    u32 b0,b1,b2,b3;
                    ldsm_x4(b0,b1,b2,b3, kbb + ((h*32 + e*16)*AP)*2 + kb*32);
                    mma_f16(sacc[2*e  ], qf[kb][0],qf[kb][1],qf[kb][2],qf[kb][3], b0,b2);
                    mma_f16(sacc[2*e+1], qf[kb][0],qf[kb][1],qf[kb][2],qf[kb][3], b1,b3);
                }
            }

            u32 pa[2][4];
            #pragma unroll
            for (int nb=0; nb<4; nb++){
                float p0 = __expf(sacc[nb][0]);
                float p1 = __expf(sacc[nb][1]);
                float p2 = __expf(sacc[nb][2]);
                float p3 = __expf(sacc[nb][3]);
                lsum0 += p0 + p1;
                lsum1 += p2 + p3;
                pa[nb>>1][(nb&1)*2 + 0] = h2(p0, p1);
                pa[nb>>1][(nb&1)*2 + 1] = h2(p2, p3);
            }

            #pragma unroll
            for (int j=0; j<2; j++){
                int kc = h*2 + j;
                #pragma unroll
                for (int np=0; np<4; np++){
                    u32 b0,b1,b2,b3;
                    ldsm_x4t(b0,b1,b2,b3, vbb + (kc*16*AP)*2 + np*32);
                    mma_f16(oacc[np*2  ], pa[j][0],pa[j][1],pa[j][2],pa[j][3], b0,b1);
                    mma_f16(oacc[np*2+1], pa[j][0],pa[j][1],pa[j][2],pa[j][3], b2,b3);
                }
            }
        }
        __syncthreads();
        if (t + 2 < 16) issue_kv(t0 + t + 2, t&1);
    }

    lsum0 += __shfl_xor_sync(0xffffffffu, lsum0, 1);
    lsum0 += __shfl_xor_sync(0xffffffffu, lsum0, 2);
    lsum1 += __shfl_xor_sync(0xffffffffu, lsum1, 1);
    lsum1 += __shfl_xor_sync(0xffffffffu, lsum1, 2);

    float* og = (z ? g_o1 : g_o0) + ((size_t)b*SEQL + qt*128)*HEAD;
    float* lg = (z ? g_l1 : g_l0) + (size_t)b*SEQL + qt*128;
    const int r = warp*16 + (lane >> 2);
    const int c = (lane & 3)*2;
    if ((lane & 3) == 0){
        lg[r]   = lsum0;
        lg[r+8] = lsum1;
    }
    #pragma unroll
    for (int nb=0; nb<8; nb++){
        *(float2*)&og[(size_t)r*HEAD + nb*8 + c] =
            make_float2(oacc[nb][0], oacc[nb][1]);
        *(float2*)&og[(size_t)(r+8)*HEAD + nb*8 + c] =
            make_float2(oacc[nb][2], oacc[nb][3]);
    }
}

// ============================================================================
// Kernel 3: FUSED combine + output projection, persistent m-tile.
// grid(128), 256 thr. Combine o0+o1 -> ctx hi/lo in smem ONCE, then loop
// 12 n-tiles with double-buffered cp.async Wo(hi/lo) tiles. A-frags hoisted.
// ============================================================================
#define CP 72
#define OP 72
#define F_CS_HI 0                        // 128*72 hw
#define F_CS_LO (128*CP)
#define F_WS0_HI (2*128*CP)              // per buf: hi 64*72 + lo 64*72
#define F_WS0_LO (F_WS0_HI + 64*OP)
#define F_WS1_HI (F_WS0_HI + 2*64*OP)
#define F_WS1_LO (F_WS1_HI + 64*OP)
#define OPROJ_SMEM ((2*128*CP + 4*64*OP)*2)   // 73728 B

__global__ __launch_bounds__(256) void oproj_fused(
    const float* __restrict__ bo,
    float* __restrict__ out)
{
    extern __shared__ u16 smo[];
    const int tid  = threadIdx.x;
    const int warp = tid >> 5;
    const int lane = tid & 31;
    const int m0 = blockIdx.x * 128;
    const u32 smb = smem_u32(smo);

    auto issue_wo = [&](int nt, int buf){
        u32 base_hi = smb + (u32)(buf ? F_WS1_HI : F_WS0_HI)*2;
        u32 base_lo = smb + (u32)(buf ? F_WS1_LO : F_WS0_LO)*2;
        int n0 = nt*64;
        #pragma unroll
        for (int i=0;i<2;i++){
            int slot = tid + i*256;
            int row = slot >> 3, ch = slot & 7;
            u32 off = (u32)(row*OP + ch*8)*2;
            const size_t src = (size_t)row*HIDDEN + n0 + ch*8;
            cp16(base_hi + off, &g_wo_hi[src]);
            cp16(base_lo + off, &g_wo_lo[src]);
        }
        CP_COMMIT();
    };

    // kick off Wo tiles 0 and 1 first so they fly during the combine
    issue_wo(0, 0);
    issue_wo(1, 1);

    // ---- combine: ctx = (o0+o1)/(l0+l1), split f16 hi/lo into smem ----
    #pragma unroll
    for (int i=0;i<4;i++){
        int slot = tid + i*256;           // 1024 slots x 8 elems
        int row = slot >> 3, c8 = (slot & 7)*8;
        int grow = m0 + row;
        float inv = 1.0f / (g_l0[grow] + g_l1[grow]);
        const size_t e = (size_t)grow*HEAD + c8;
        uint4 hiv, lov;
        {
            float4 o0 = *(const float4*)&g_o0[e];
            float4 o1 = *(const float4*)&g_o1[e];
            h2split((o0.x+o1.x)*inv, (o0.y+o1.y)*inv, hiv.x, lov.x);
            h2split((o0.z+o1.z)*inv, (o0.w+o1.w)*inv, hiv.y, lov.y);
        }
        {
            float4 o0 = *(const float4*)&g_o0[e+4];
            float4 o1 = *(const float4*)&g_o1[e+4];
            h2split((o0.x+o1.x)*inv, (o0.y+o1.y)*inv, hiv.z, lov.z);
            h2split((o0.z+o1.z)*inv, (o0.w+o1.w)*inv, hiv.w, lov.w);
        }
        *(uint4*)&smo[F_CS_HI + row*CP + c8] = hiv;
        *(uint4*)&smo[F_CS_LO + row*CP + c8] = lov;
    }
    __syncthreads();

    // ---- hoist ctx A-fragments (hi + lo) ----
    const int l15 = lane & 15;
    const int lhi = ((lane >> 4) & 1) * 8;
    const u32 a_off = ((warp*16 + l15)*CP + lhi)*2;
    const u32 a_hi = smb + F_CS_HI*2 + a_off;
    const u32 a_lo = smb + F_CS_LO*2 + a_off;
    u32 ahf[4][4], alf[4][4];
    #pragma unroll
    for (int kb=0; kb<4; kb++){
        ldsm_x4(ahf[kb][0], ahf[kb][1], ahf[kb][2], ahf[kb][3], a_hi + kb*32);
        ldsm_x4(alf[kb][0], alf[kb][1], alf[kb][2], alf[kb][3], a_lo + kb*32);
    }

    const u32 b_off = (l15*OP + lhi)*2;
    const u32 bh_[2] = { smb + F_WS0_HI*2 + b_off, smb + F_WS1_HI*2 + b_off };
    const u32 bl_[2] = { smb + F_WS0_LO*2 + b_off, smb + F_WS1_LO*2 + b_off };

    const int r = m0 + warp*16 + (lane >> 2);
    const int c = (lane & 3)*2;

    for (int nt=0; nt<12; nt++){
        if (nt < 11) CP_WAIT1(); else CP_WAIT0();
        __syncthreads();

        float acc[8][4];
        #pragma unroll
        for (int i=0;i<8;i++)
            #pragma unroll
            for (int j=0;j<4;j++) acc[i][j] = 0.f;

        const u32 bh = bh_[nt&1], bl = bl_[nt&1];
        #pragma unroll
        for (int pass=0; pass<3; pass++){
            const u32 (*af)[4] = (pass==2) ? alf : ahf;
            const u32 bb = (pass==1) ? bl : bh;
            #pragma unroll
            for (int kb=0; kb<4; kb++){
                #pragma unroll
                for (int n16=0; n16<4; n16++){
                    u32 b0,b1,b2,b3;
                    ldsm_x4t(b0,b1,b2,b3, bb + (kb*16*OP)*2 + n16*32);
                    mma_f16(acc[n16*2  ], af[kb][0],af[kb][1],af[kb][2],af[kb][3], b0,b1);
                    mma_f16(acc[n16*2+1], af[kb][0],af[kb][1],af[kb][2],af[kb][3], b2,b3);
                }
            }
        }

        __syncthreads();                    // all warps done reading buf nt&1
        if (nt + 2 < 12) issue_wo(nt+2, nt&1);

        const int n0 = nt*64;
        #pragma unroll
        for (int nb=0; nb<8; nb++){
            int n = n0 + nb*8 + c;
            float b0v = bo[n], b1v = bo[n+1];
            *(float2*)&out[(size_t)r*HIDDEN + n] =
                make_float2(acc[nb][0]+b0v, acc[nb][1]+b1v);
            *(float2*)&out[(size_t)(r+8)*HIDDEN + n] =
                make_float2(acc[nb][2]+b0v, acc[nb][3]+b1v);
        }
    }
}

extern "C" void kernel_launch(void* const* d_in, const int* in_sizes, int n_in,
                              void* d_out, int out_size)
{
    const float* x  = (const float*)d_in[0];
    const float* Wq = (const float*)d_in[1];
    const float* bq = (const float*)d_in[2];
    const float* Wk = (const float*)d_in[3];
    const float* bk = (const float*)d_in[4];
    const float* Wv = (const float*)d_in[5];
    const float* bv = (const float*)d_in[6];
    const float* Wo = (const float*)d_in[7];
    const float* bo = (const float*)d_in[8];
    float* out = (float*)d_out;

    cudaFuncSetAttribute(qkv_hmma,         cudaFuncAttributeMaxDynamicSharedMemorySize, QKV_SMEM);
    cudaFuncSetAttribute(attn_hmma_kernel, cudaFuncAttributeMaxDynamicSharedMemorySize, ATTN_SMEM);
    cudaFuncSetAttribute(oproj_fused,      cudaFuncAttributeMaxDynamicSharedMemorySize, OPROJ_SMEM);

    wcvt_kernel<<<384, 256>>>(Wq, Wk, Wv, Wo);
    qkv_hmma<<<128, 256, QKV_SMEM>>>(x, bq, bk, bv);
    attn_hmma_kernel<<<dim3(32,4,2), 256, ATTN_SMEM>>>();
    oproj_fused<<<128, 256, OPROJ_SMEM>>>(bo, out);
}

// round 12
// speedup vs baseline: 1.0301x; 1.0301x over previous
#include <cuda_runtime.h>
#include <cuda_fp16.h>

#define HIDDEN 768
#define HEAD 64
#define BATCH 4
#define SEQL 4096
#define MTOT (BATCH*SEQL)

typedef unsigned long long u64;
typedef unsigned int u32;
typedef unsigned short u16;

// scratch — __device__ globals, no allocation
__device__ __align__(256) u16 g_qh[MTOT*HEAD];
__device__ __align__(256) u16 g_kh[MTOT*HEAD];
__device__ __align__(256) u16 g_vh[MTOT*HEAD];
__device__ __align__(256) u16 g_wh[3*HIDDEN*HEAD];
__device__ __align__(256) u16 g_wo_hi[HEAD*HIDDEN];
__device__ __align__(256) u16 g_wo_lo[HEAD*HIDDEN];
__device__ __align__(256) float g_o0[MTOT*HEAD];
__device__ __align__(256) float g_o1[MTOT*HEAD];
__device__ __align__(256) float g_l0[MTOT];
__device__ __align__(256) float g_l1[MTOT];

// ---------------------------------------------------------------------------
// helpers
// ---------------------------------------------------------------------------
__device__ __forceinline__ u32 smem_u32(const void* p){
    u32 a; asm("{ .reg .u64 t; cvta.to.shared.u64 t, %1; cvt.u32.u64 %0, t; }" : "=r"(a) : "l"(p));
    return a;
}
__device__ __forceinline__ void ldsm_x4(u32 &r0, u32 &r1, u32 &r2, u32 &r3, u32 addr){
    asm volatile("ldmatrix.sync.aligned.m8n8.x4.shared.b16 {%0,%1,%2,%3}, [%4];"
        : "=r"(r0), "=r"(r1), "=r"(r2), "=r"(r3) : "r"(addr));
}
__device__ __forceinline__ void ldsm_x4t(u32 &r0, u32 &r1, u32 &r2, u32 &r3, u32 addr){
    asm volatile("ldmatrix.sync.aligned.m8n8.x4.trans.shared.b16 {%0,%1,%2,%3}, [%4];"
        : "=r"(r0), "=r"(r1), "=r"(r2), "=r"(r3) : "r"(addr));
}
__device__ __forceinline__ void mma_f16(float* c, u32 a0, u32 a1, u32 a2, u32 a3, u32 b0, u32 b1){
    asm volatile("mma.sync.aligned.m16n8k16.row.col.f32.f16.f16.f32 "
        "{%0,%1,%2,%3}, {%4,%5,%6,%7}, {%8,%9}, {%0,%1,%2,%3};"
        : "+f"(c[0]), "+f"(c[1]), "+f"(c[2]), "+f"(c[3])
        : "r"(a0), "r"(a1), "r"(a2), "r"(a3), "r"(b0), "r"(b1));
}
__device__ __forceinline__ u32 h2(float a, float b){
    __half2 h = __floats2half2_rn(a, b);
    return *(u32*)&h;
}
__device__ __forceinline__ void h2split(float a, float b, u32 &hi, u32 &lo){
    __half ha = __float2half_rn(a), hb = __float2half_rn(b);
    __half2 hh = __halves2half2(ha, hb);
    hi = *(u32*)&hh;
    __half2 ll = __floats2half2_rn(a - __half2float(ha), b - __half2float(hb));
    lo = *(u32*)&ll;
}
__device__ __forceinline__ void cp16(u32 dst, const void* src){
    asm volatile("cp.async.cg.shared.global [%0], [%1], 16;" :: "r"(dst), "l"(src));
}
#define CP_COMMIT() asm volatile("cp.async.commit_group;" ::: "memory")
#define CP_WAIT0()  asm volatile("cp.async.wait_group 0;" ::: "memory")
#define CP_WAIT1()  asm volatile("cp.async.wait_group 1;" ::: "memory")

// ============================================================================
// Kernel 0: weight pre-convert. Wq/Wk/Wv -> f16; Wo -> f16 hi/lo split.
// ============================================================================
__global__ void wcvt_kernel(const float* __restrict__ Wq,
                            const float* __restrict__ Wk,
                            const float* __restrict__ Wv,
                            const float* __restrict__ Wo)
{
    int slot = blockIdx.x*256 + threadIdx.x;
    if (slot < 73728){
        int w = slot / 24576, rem = slot % 24576;
        const float* W = (w==0)?Wq:((w==1)?Wk:Wv);
        float2 v = *(const float2*)&W[rem*2];
        *(u32*)&g_wh[w*(HIDDEN*HEAD) + rem*2] = h2(v.x, v.y);
    } else {
        int s = slot - 73728;
        float2 v = *(const float2*)&Wo[s*2];
        u32 hi, lo; h2split(v.x, v.y, hi, lo);
        *(u32*)&g_wo_hi[s*2] = hi;
        *(u32*)&g_wo_lo[s*2] = lo;
    }
}

// ============================================================================
// Kernel 1: merged QKV projection (unchanged from R7-R11 pass).
// ============================================================================
#define QKV_P 72
#define QKV_XS0 0
#define QKV_XS1 (128*QKV_P)
#define QKV_WS0 (2*128*QKV_P)
#define QKV_WS1 (QKV_WS0 + 3*64*QKV_P)
#define QKV_SMEM ((2*128*QKV_P + 2*3*64*QKV_P)*2)   // 92160 B

__global__ __launch_bounds__(256) void qkv_hmma(
    const float* __restrict__ x,
    const float* __restrict__ bq,
    const float* __restrict__ bk,
    const float* __restrict__ bv)
{
    extern __shared__ u16 smq[];
    const int tid  = threadIdx.x;
    const int warp = tid >> 5;
    const int lane = tid & 31;
    const int m0 = blockIdx.x * 128;

    const u32 smb = smem_u32(smq);
    const int l15 = lane & 15;
    const int lhi = ((lane >> 4) & 1) * 8;
    const u32 xa[2] = { smb + (QKV_XS0 + (warp*16 + l15)*QKV_P + lhi)*2,
                        smb + (QKV_XS1 + (warp*16 + l15)*QKV_P + lhi)*2 };
    const u32 wb[2] = { smb + (QKV_WS0 + l15*QKV_P + lhi)*2,
                        smb + (QKV_WS1 + l15*QKV_P + lhi)*2 };

    float4 xstage[8];

    auto stage_x = [&](int kk){
        #pragma unroll
        for (int i=0;i<8;i++){
            int slot = tid + i*256;
            int row = slot >> 4, c4 = slot & 15;
            xstage[i] = *(const float4*)&x[(size_t)(m0+row)*HIDDEN + kk + c4*4];
        }
    };
    auto store_x = [&](int buf){
        u32 base = buf ? (u32)QKV_XS1 : (u32)QKV_XS0;
        #pragma unroll
        for (int i=0;i<8;i++){
            int slot = tid + i*256;
            int row = slot >> 4, c4 = slot & 15;
            *(uint2*)&smq[base + row*QKV_P + c4*4] =
                make_uint2(h2(xstage[i].x, xstage[i].y), h2(xstage[i].z, xstage[i].w));
        }
    };
    auto issue_w = [&](int kk, int buf){
        u32 base = smb + (buf ? (u32)QKV_WS1 : (u32)QKV_WS0)*2;
        #pragma unroll
        for (int i=0;i<6;i++){
            int slot = tid + i*256;
            int w = slot >> 9, row = (slot >> 3) & 63, ch = slot & 7;
            u32 dst = base + ((w*64 + row)*QKV_P + ch*8)*2;
            const u16* src = &g_wh[(size_t)w*(HIDDEN*HEAD) + (size_t)(kk+row)*HEAD + ch*8];
            cp16(dst, src);
        }
        CP_COMMIT();
    };

    float acc[3][8][4];
    #pragma unroll
    for (int w=0;w<3;w++)
        #pragma unroll
        for (int i=0;i<8;i++)
            #pragma unroll
            for (int j=0;j<4;j++) acc[w][i][j] = 0.f;

    stage_x(0);
    issue_w(0, 0);
    store_x(0);
    issue_w(64, 1);
    stage_x(64);

    for (int t=0; t<12; t++){
        if (t < 11) CP_WAIT1(); else CP_WAIT0();
        __syncthreads();

        const u32 xab = xa[t&1];
        const u32 wbb = wb[t&1];
        #pragma unroll
        for (int kb=0; kb<4; kb++){
            u32 a0,a1,a2,a3;
            ldsm_x4(a0,a1,a2,a3, xab + kb*32);
            #pragma unroll
            for (int w=0; w<3; w++){
                u32 rowoff = ((u32)(w*64 + kb*16)*QKV_P)*2;
                #pragma unroll
                for (int n16=0; n16<4; n16++){
                    u32 b0,b1,b2,b3;
                    ldsm_x4t(b0,b1,b2,b3, wbb + rowoff + n16*32);
                    mma_f16(acc[w][n16*2  ], a0,a1,a2,a3, b0,b1);
                    mma_f16(acc[w][n16*2+1], a0,a1,a2,a3, b2,b3);
                }
            }
        }

        if (t < 11) store_x((t+1)&1);
        __syncthreads();
        if (t < 10){
            issue_w((t+2)*64, t&1);
            stage_x((t+2)*64);
        }
    }

    const int r = m0 + warp*16 + (lane >> 2);
    const int c = (lane & 3)*2;
    #pragma unroll
    for (int w=0; w<3; w++){
        const float* bias = (w==0)?bq:((w==1)?bk:bv);
        u16* out = (w==0)?g_qh:((w==1)?g_kh:g_vh);
        const float scale = (w==0)?0.125f:1.0f;
        #pragma unroll
        for (int nb=0; nb<8; nb++){
            int n = nb*8 + c;
            float b0v = bias[n], b1v = bias[n+1];
            *(u32*)&out[(size_t)r*HEAD + n] =
                h2((acc[w][nb][0]+b0v)*scale, (acc[w][nb][1]+b1v)*scale);
            *(u32*)&out[(size_t)(r+8)*HEAD + n] =
                h2((acc[w][nb][2]+b0v)*scale, (acc[w][nb][3]+b1v)*scale);
        }
    }
}

// ============================================================================
// Kernel 2: HMMA flash attention (unchanged from R10/R11 pass).
// ============================================================================
#define AP 72
#define A_Q  0
#define A_K0 (128*AP)
#define A_K1 (2*128*AP)
#define A_V0 (3*128*AP)
#define A_V1 (4*128*AP)
#define ATTN_SMEM (5*128*AP*2)   // 92160 B

__global__ __launch_bounds__(256, 2) void attn_hmma_kernel()
{
    extern __shared__ u16 smh[];
    const int tid  = threadIdx.x;
    const int warp = tid >> 5;
    const int lane = tid & 31;
    const int b = blockIdx.y, qt = blockIdx.x, z = blockIdx.z;
    const int t0 = z*16;

    const u16* __restrict__ qg = g_qh + ((size_t)b*SEQL + qt*128)*HEAD;
    const u16* __restrict__ kg = g_kh + (size_t)b*SEQL*HEAD;
    const u16* __restrict__ vg = g_vh + (size_t)b*SEQL*HEAD;

    const u32 smb = smem_u32(smh);
    const int l15 = lane & 15;
    const int lhi = ((lane >> 4) & 1) * 8;
    const u32 qbase = smb + (A_Q + (warp*16 + l15)*AP + lhi)*2;
    const u32 kb_[2] = { smb + (A_K0 + l15*AP + lhi)*2, smb + (A_K1 + l15*AP + lhi)*2 };
    const u32 vb_[2] = { smb + (A_V0 + l15*AP + lhi)*2, smb + (A_V1 + l15*AP + lhi)*2 };

    auto issue_kv = [&](int t, int buf){
        u32 kdst = smb + ((buf ? A_K1 : A_K0))*2;
        u32 vdst = smb + ((buf ? A_V1 : A_V0))*2;
        const u16* ks = kg + (size_t)t*128*HEAD;
        const u16* vs = vg + (size_t)t*128*HEAD;
        #pragma unroll
        for (int i=0;i<4;i++){
            int slot = tid + i*256;
            int row = slot >> 3, ch = slot & 7;
            u32 off = (u32)(row*AP + ch*8)*2;
            cp16(kdst + off, ks + row*HEAD + ch*8);
            cp16(vdst + off, vs + row*HEAD + ch*8);
        }
        CP_COMMIT();
    };

    {
        #pragma unroll
        for (int i=0;i<4;i++){
            int slot = tid + i*256;
            int row = slot >> 3, ch = slot & 7;
            cp16(smb + (A_Q + row*AP + ch*8)*2, qg + row*HEAD + ch*8);
        }
        u32 kdst = smb + A_K0*2, vdst = smb + A_V0*2;
        const u16* ks = kg + (size_t)t0*128*HEAD;
        const u16* vs = vg + (size_t)t0*128*HEAD;
        #pragma unroll
        for (int i=0;i<4;i++){
            int slot = tid + i*256;
            int row = slot >> 3, ch = slot & 7;
            u32 off = (u32)(row*AP + ch*8)*2;
            cp16(kdst + off, ks + row*HEAD + ch*8);
            cp16(vdst + off, vs + row*HEAD + ch*8);
        }
        CP_COMMIT();
        issue_kv(t0+1, 1);
    }

    float oacc[8][4];
    #pragma unroll
    for (int i=0;i<8;i++)
        #pragma unroll
        for (int j=0;j<4;j++) oacc[i][j] = 0.f;
    float lsum0 = 0.f, lsum1 = 0.f;
    u32 qf[4][4];
    bool qloaded = false;

    for (int t = 0; t < 16; t++){
        if (t < 15) CP_WAIT1(); else CP_WAIT0();
        __syncthreads();

        if (!qloaded){
            #pragma unroll
            for (int kb=0; kb<4; kb++)
                ldsm_x4(qf[kb][0], qf[kb][1], qf[kb][2], qf[kb][3], qbase + kb*32);
            qloaded = true;
        }

        const u32 kbb = kb_[t&1];
        const u32 vbb = vb_[t&1];

        #pragma unroll
        for (int h=0; h<4; h++){
            float sacc[4][4];
            #pragma unroll
            for (int i=0;i<4;i++)
                #pragma unroll
                for (int j=0;j<4;j++) sacc[i][j] = 0.f;

            #pragma unroll
            for (int kb=0; kb<4; kb++){
                #pragma unroll
                for (int e=0; e<2; e++){
                    u32 b0,b1,b2,b3;
                    ldsm_x4(b0,b1,b2,b3, kbb + ((h*32 + e*16)*AP)*2 + kb*32);
                    mma_f16(sacc[2*e  ], qf[kb][0],qf[kb][1],qf[kb][2],qf[kb][3], b0,b2);
                    mma_f16(sacc[2*e+1], qf[kb][0],qf[kb][1],qf[kb][2],qf[kb][3], b1,b3);
                }
            }

            u32 pa[2][4];
            #pragma unroll
            for (int nb=0; nb<4; nb++){
                float p0 = __expf(sacc[nb][0]);
                float p1 = __expf(sacc[nb][1]);
                float p2 = __expf(sacc[nb][2]);
                float p3 = __expf(sacc[nb][3]);
                lsum0 += p0 + p1;
                lsum1 += p2 + p3;
                pa[nb>>1][(nb&1)*2 + 0] = h2(p0, p1);
                pa[nb>>1][(nb&1)*2 + 1] = h2(p2, p3);
            }

            #pragma unroll
            for (int j=0; j<2; j++){
                int kc = h*2 + j;
                #pragma unroll
                for (int np=0; np<4; np++){
                    u32 b0,b1,b2,b3;
                    ldsm_x4t(b0,b1,b2,b3, vbb + (kc*16*AP)*2 + np*32);
                    mma_f16(oacc[np*2  ], pa[j][0],pa[j][1],pa[j][2],pa[j][3], b0,b1);
                    mma_f16(oacc[np*2+1], pa[j][0],pa[j][1],pa[j][2],pa[j][3], b2,b3);
                }
            }
        }
        __syncthreads();
        if (t + 2 < 16) issue_kv(t0 + t + 2, t&1);
    }

    lsum0 += __shfl_xor_sync(0xffffffffu, lsum0, 1);
    lsum0 += __shfl_xor_sync(0xffffffffu, lsum0, 2);
    lsum1 += __shfl_xor_sync(0xffffffffu, lsum1, 1);
    lsum1 += __shfl_xor_sync(0xffffffffu, lsum1, 2);

    float* og = (z ? g_o1 : g_o0) + ((size_t)b*SEQL + qt*128)*HEAD;
    float* lg = (z ? g_l1 : g_l0) + (size_t)b*SEQL + qt*128;
    const int r = warp*16 + (lane >> 2);
    const int c = (lane & 3)*2;
    if ((lane & 3) == 0){
        lg[r]   = lsum0;
        lg[r+8] = lsum1;
    }
    #pragma unroll
    for (int nb=0; nb<8; nb++){
        *(float2*)&og[(size_t)r*HEAD + nb*8 + c] =
            make_float2(oacc[nb][0], oacc[nb][1]);
        *(float2*)&og[(size_t)(r+8)*HEAD + nb*8 + c] =
            make_float2(oacc[nb][2], oacc[nb][3]);
    }
}

// ============================================================================
// Kernel 3: FUSED combine + output projection, 256 CTAs x 64-row m-tiles.
// 8 warps = 4 row-groups x 2 n-halves. 2 CTAs/SM, single wave.
// ============================================================================
#define CP 72
#define OP 72
#define F_CS_HI 0                        // 64*72 hw
#define F_CS_LO (64*CP)
#define F_WS0_HI (2*64*CP)
#define F_WS0_LO (F_WS0_HI + 64*OP)
#define F_WS1_HI (F_WS0_HI + 2*64*OP)
#define F_WS1_LO (F_WS1_HI + 64*OP)
#define OPROJ_SMEM ((2*64*CP + 4*64*OP)*2)   // 55296 B

__global__ __launch_bounds__(256, 2) void oproj_fused(
    const float* __restrict__ bo,
    float* __restrict__ out)
{
    extern __shared__ u16 smo[];
    const int tid  = threadIdx.x;
    const int warp = tid >> 5;
    const int lane = tid & 31;
    const int wm = warp & 3;            // row group (16 rows)
    const int wn = warp >> 2;           // n half (32 cols)
    const int m0 = blockIdx.x * 64;
    const u32 smb = smem_u32(smo);

    auto issue_wo = [&](int nt, int buf){
        u32 base_hi = smb + (u32)(buf ? F_WS1_HI : F_WS0_HI)*2;
        u32 base_lo = smb + (u32)(buf ? F_WS1_LO : F_WS0_LO)*2;
        int n0 = nt*64;
        #pragma unroll
        for (int i=0;i<2;i++){
            int slot = tid + i*256;
            int row = slot >> 3, ch = slot & 7;
            u32 off = (u32)(row*OP + ch*8)*2;
            const size_t src = (size_t)row*HIDDEN + n0 + ch*8;
            cp16(base_hi + off, &g_wo_hi[src]);
            cp16(base_lo + off, &g_wo_lo[src]);
        }
        CP_COMMIT();
    };

    issue_wo(0, 0);
    issue_wo(1, 1);

    // ---- combine: ctx = (o0+o1)/(l0+l1), split f16 hi/lo into smem ----
    // 64 rows x 64 cols = 512 slots of 8 elems; 2 per thread
    #pragma unroll
    for (int i=0;i<2;i++){
        int slot = tid + i*256;
        int row = slot >> 3, c8 = (slot & 7)*8;
        int grow = m0 + row;
        float inv = 1.0f / (g_l0[grow] + g_l1[grow]);
        const size_t e = (size_t)grow*HEAD + c8;
        uint4 hiv, lov;
        {
            float4 o0 = *(const float4*)&g_o0[e];
            float4 o1 = *(const float4*)&g_o1[e];
            h2split((o0.x+o1.x)*inv, (o0.y+o1.y)*inv, hiv.x, lov.x);
            h2split((o0.z+o1.z)*inv, (o0.w+o1.w)*inv, hiv.y, lov.y);
        }
        {
            float4 o0 = *(const float4*)&g_o0[e+4];
            float4 o1 = *(const float4*)&g_o1[e+4];
            h2split((o0.x+o1.x)*inv, (o0.y+o1.y)*inv, hiv.z, lov.z);
            h2split((o0.z+o1.z)*inv, (o0.w+o1.w)*inv, hiv.w, lov.w);
        }
        *(uint4*)&smo[F_CS_HI + row*CP + c8] = hiv;
        *(uint4*)&smo[F_CS_LO + row*CP + c8] = lov;
    }
    __syncthreads();

    // ---- hoist ctx A-fragments (hi + lo) for this warp's 16 rows ----
    const int l15 = lane & 15;
    const int lhi = ((lane >> 4) & 1) * 8;
    const u32 a_off = ((wm*16 + l15)*CP + lhi)*2;
    const u32 a_hi = smb + F_CS_HI*2 + a_off;
    const u32 a_lo = smb + F_CS_LO*2 + a_off;
    u32 ahf[4][4], alf[4][4];
    #pragma unroll
    for (int kb=0; kb<4; kb++){
        ldsm_x4(ahf[kb][0], ahf[kb][1], ahf[kb][2], ahf[kb][3], a_hi + kb*32);
        ldsm_x4(alf[kb][0], alf[kb][1], alf[kb][2], alf[kb][3], a_lo + kb*32);
    }

    // B base: rows via l15, col base = wn*32 cols (64 bytes) + lhi
    const u32 b_off = (l15*OP + wn*32 + lhi)*2;
    const u32 bh_[2] = { smb + F_WS0_HI*2 + b_off, smb + F_WS1_HI*2 + b_off };
    const u32 bl_[2] = { smb + F_WS0_LO*2 + b_off, smb + F_WS1_LO*2 + b_off };

    const int r = m0 + wm*16 + (lane >> 2);
    const int c = (lane & 3)*2;

    for (int nt=0; nt<12; nt++){
        if (nt < 11) CP_WAIT1(); else CP_WAIT0();
        __syncthreads();

        float acc[4][4];
        #pragma unroll
        for (int i=0;i<4;i++)
            #pragma unroll
            for (int j=0;j<4;j++) acc[i][j] = 0.f;

        const u32 bh = bh_[nt&1], bl = bl_[nt&1];
        #pragma unroll
        for (int pass=0; pass<3; pass++){
            const u32 (*af)[4] = (pass==2) ? alf : ahf;
            const u32 bb = (pass==1) ? bl : bh;
            #pragma unroll
            for (int kb=0; kb<4; kb++){
                #pragma unroll
                for (int n16=0; n16<2; n16++){
                    u32 b0,b1,b2,b3;
                    ldsm_x4t(b0,b1,b2,b3, bb + (kb*16*OP)*2 + n16*32);
                    mma_f16(acc[n16*2  ], af[kb][0],af[kb][1],af[kb][2],af[kb][3], b0,b1);
                    mma_f16(acc[n16*2+1], af[kb][0],af[kb][1],af[kb][2],af[kb][3], b2,b3);
                }
            }
        }

        __syncthreads();
        if (nt + 2 < 12) issue_wo(nt+2, nt&1);

        const int n0 = nt*64 + wn*32;
        #pragma unroll
        for (int nb=0; nb<4; nb++){
            int n = n0 + nb*8 + c;
            float b0v = bo[n], b1v = bo[n+1];
            *(float2*)&out[(size_t)r*HIDDEN + n] =
                make_float2(acc[nb][0]+b0v, acc[nb][1]+b1v);
            *(float2*)&out[(size_t)(r+8)*HIDDEN + n] =
                make_float2(acc[nb][2]+b0v, acc[nb][3]+b1v);
        }
    }
}

extern "C" void kernel_launch(void* const* d_in, const int* in_sizes, int n_in,
                              void* d_out, int out_size)
{
    const float* x  = (const float*)d_in[0];
    const float* Wq = (const float*)d_in[1];
    const float* bq = (const float*)d_in[2];
    const float* Wk = (const float*)d_in[3];
    const float* bk = (const float*)d_in[4];
    const float* Wv = (const float*)d_in[5];
    const float* bv = (const float*)d_in[6];
    const float* Wo = (const float*)d_in[7];
    const float* bo = (const float*)d_in[8];
    float* out = (float*)d_out;

    cudaFuncSetAttribute(qkv_hmma,         cudaFuncAttributeMaxDynamicSharedMemorySize, QKV_SMEM);
    cudaFuncSetAttribute(attn_hmma_kernel, cudaFuncAttributeMaxDynamicSharedMemorySize, ATTN_SMEM);
    cudaFuncSetAttribute(oproj_fused,      cudaFuncAttributeMaxDynamicSharedMemorySize, OPROJ_SMEM);

    wcvt_kernel<<<384, 256>>>(Wq, Wk, Wv, Wo);
    qkv_hmma<<<128, 256, QKV_SMEM>>>(x, bq, bk, bv);
    attn_hmma_kernel<<<dim3(32,4,2), 256, ATTN_SMEM>>>();
    oproj_fused<<<256, 256, OPROJ_SMEM>>>(bo, out);
}

// round 13
// speedup vs baseline: 1.1021x; 1.0700x over previous
#include <cuda_runtime.h>
#include <cuda_fp16.h>

#define HIDDEN 768
#define HEAD 64
#define BATCH 4
#define SEQL 4096
#define MTOT (BATCH*SEQL)

typedef unsigned long long u64;
typedef unsigned int u32;
typedef unsigned short u16;

// scratch — __device__ globals, no allocation
__device__ __align__(256) u16 g_qh[MTOT*HEAD];
__device__ __align__(256) u16 g_kh[MTOT*HEAD];
__device__ __align__(256) u16 g_vh[MTOT*HEAD];
__device__ __align__(256) u16 g_wh[3*HIDDEN*HEAD];
__device__ __align__(256) u16 g_wo[HEAD*HIDDEN];
__device__ __align__(256) float g_o0[MTOT*HEAD];
__device__ __align__(256) float g_o1[MTOT*HEAD];
__device__ __align__(256) float g_l0[MTOT];
__device__ __align__(256) float g_l1[MTOT];
__device__ __align__(256) u16 g_ctxh[MTOT*HEAD];

// ---------------------------------------------------------------------------
// helpers
// ---------------------------------------------------------------------------
__device__ __forceinline__ u32 smem_u32(const void* p){
    u32 a; asm("{ .reg .u64 t; cvta.to.shared.u64 t, %1; cvt.u32.u64 %0, t; }" : "=r"(a) : "l"(p));
    return a;
}
__device__ __forceinline__ void ldsm_x4(u32 &r0, u32 &r1, u32 &r2, u32 &r3, u32 addr){
    asm volatile("ldmatrix.sync.aligned.m8n8.x4.shared.b16 {%0,%1,%2,%3}, [%4];"
        : "=r"(r0), "=r"(r1), "=r"(r2), "=r"(r3) : "r"(addr));
}
__device__ __forceinline__ void ldsm_x4t(u32 &r0, u32 &r1, u32 &r2, u32 &r3, u32 addr){
    asm volatile("ldmatrix.sync.aligned.m8n8.x4.trans.shared.b16 {%0,%1,%2,%3}, [%4];"
        : "=r"(r0), "=r"(r1), "=r"(r2), "=r"(r3) : "r"(addr));
}
__device__ __forceinline__ void mma_f16(float* c, u32 a0, u32 a1, u32 a2, u32 a3, u32 b0, u32 b1){
    asm volatile("mma.sync.aligned.m16n8k16.row.col.f32.f16.f16.f32 "
        "{%0,%1,%2,%3}, {%4,%5,%6,%7}, {%8,%9}, {%0,%1,%2,%3};"
        : "+f"(c[0]), "+f"(c[1]), "+f"(c[2]), "+f"(c[3])
        : "r"(a0), "r"(a1), "r"(a2), "r"(a3), "r"(b0), "r"(b1));
}
__device__ __forceinline__ u32 h2(float a, float b){
    __half2 h = __floats2half2_rn(a, b);
    return *(u32*)&h;
}
__device__ __forceinline__ void cp16(u32 dst, const void* src){
    asm volatile("cp.async.cg.shared.global [%0], [%1], 16;" :: "r"(dst), "l"(src));
}
#define CP_COMMIT() asm volatile("cp.async.commit_group;" ::: "memory")
#define CP_WAIT0()  asm volatile("cp.async.wait_group 0;" ::: "memory")
#define CP_WAIT1()  asm volatile("cp.async.wait_group 1;" ::: "memory")

// ============================================================================
// Kernel 0: weight pre-convert. Wq/Wk/Wv/Wo -> f16.
// ============================================================================
__global__ void wcvt_kernel(const float* __restrict__ Wq,
                            const float* __restrict__ Wk,
                            const float* __restrict__ Wv,
                            const float* __restrict__ Wo)
{
    int slot = blockIdx.x*256 + threadIdx.x;
    if (slot < 73728){
        int w = slot / 24576, rem = slot % 24576;
        const float* W = (w==0)?Wq:((w==1)?Wk:Wv);
        float2 v = *(const float2*)&W[rem*2];
        *(u32*)&g_wh[w*(HIDDEN*HEAD) + rem*2] = h2(v.x, v.y);
    } else {
        int s = slot - 73728;
        float2 v = *(const float2*)&Wo[s*2];
        *(u32*)&g_wo[s*2] = h2(v.x, v.y);
    }
}

// ============================================================================
// Kernel 1: merged QKV projection, 256 CTAs x 64-row m-tiles, 2 CTAs/SM.
// 8 warps = 4 row-groups(16) x 2 col-halves(32 of each of 3 outputs).
// K-tile 64, 12 iters, double-buffered x (reg-staged) + W (cp.async).
// ============================================================================
#define QKV_P 72
#define QKV_XS0 0
#define QKV_XS1 (64*QKV_P)
#define QKV_WS0 (2*64*QKV_P)
#define QKV_WS1 (QKV_WS0 + 3*64*QKV_P)
#define QKV_SMEM ((2*64*QKV_P + 2*3*64*QKV_P)*2)   // 73728 B

__global__ __launch_bounds__(256, 2) void qkv_hmma(
    const float* __restrict__ x,
    const float* __restrict__ bq,
    const float* __restrict__ bk,
    const float* __restrict__ bv)
{
    extern __shared__ u16 smq[];
    const int tid  = threadIdx.x;
    const int warp = tid >> 5;
    const int lane = tid & 31;
    const int wm = warp & 3;            // 16-row group
    const int wn = warp >> 2;           // 32-col half
    const int m0 = blockIdx.x * 64;

    const u32 smb = smem_u32(smq);
    const int l15 = lane & 15;
    const int lhi = ((lane >> 4) & 1) * 8;
    const u32 xa[2] = { smb + (QKV_XS0 + (wm*16 + l15)*QKV_P + lhi)*2,
                        smb + (QKV_XS1 + (wm*16 + l15)*QKV_P + lhi)*2 };
    const u32 wb[2] = { smb + (QKV_WS0 + l15*QKV_P + wn*32 + lhi)*2,
                        smb + (QKV_WS1 + l15*QKV_P + wn*32 + lhi)*2 };

    float4 xstage[4];

    auto stage_x = [&](int kk){
        #pragma unroll
        for (int i=0;i<4;i++){
            int slot = tid + i*256;          // 1024 = 64 rows x 16 c4
            int row = slot >> 4, c4 = slot & 15;
            xstage[i] = *(const float4*)&x[(size_t)(m0+row)*HIDDEN + kk + c4*4];
        }
    };
    auto store_x = [&](int buf){
        u32 base = buf ? (u32)QKV_XS1 : (u32)QKV_XS0;
        #pragma unroll
        for (int i=0;i<4;i++){
            int slot = tid + i*256;
            int row = slot >> 4, c4 = slot & 15;
            *(uint2*)&smq[base + row*QKV_P + c4*4] =
                make_uint2(h2(xstage[i].x, xstage[i].y), h2(xstage[i].z, xstage[i].w));
        }
    };
    auto issue_w = [&](int kk, int buf){
        u32 base = smb + (buf ? (u32)QKV_WS1 : (u32)QKV_WS0)*2;
        #pragma unroll
        for (int i=0;i<6;i++){
            int slot = tid + i*256;          // 1536 = 3 w x 64 rows x 8 ch
            int w = slot >> 9, row = (slot >> 3) & 63, ch = slot & 7;
            u32 dst = base + ((w*64 + row)*QKV_P + ch*8)*2;
            const u16* src = &g_wh[(size_t)w*(HIDDEN*HEAD) + (size_t)(kk+row)*HEAD + ch*8];
            cp16(dst, src);
        }
        CP_COMMIT();
    };

    float acc[3][4][4];
    #pragma unroll
    for (int w=0;w<3;w++)
        #pragma unroll
        for (int i=0;i<4;i++)
            #pragma unroll
            for (int j=0;j<4;j++) acc[w][i][j] = 0.f;

    stage_x(0);
    issue_w(0, 0);
    store_x(0);
    issue_w(64, 1);
    stage_x(64);

    for (int t=0; t<12; t++){
        if (t < 11) CP_WAIT1(); else CP_WAIT0();
        __syncthreads();

        const u32 xab = xa[t&1];
        const u32 wbb = wb[t&1];
        #pragma unroll
        for (int kb=0; kb<4; kb++){
            u32 a0,a1,a2,a3;
            ldsm_x4(a0,a1,a2,a3, xab + kb*32);
            #pragma unroll
            for (int w=0; w<3; w++){
                u32 rowoff = ((u32)(w*64 + kb*16)*QKV_P)*2;
                #pragma unroll
                for (int n16=0; n16<2; n16++){
                    u32 b0,b1,b2,b3;
                    ldsm_x4t(b0,b1,b2,b3, wbb + rowoff + n16*32);
                    mma_f16(acc[w][n16*2  ], a0,a1,a2,a3, b0,b1);
                    mma_f16(acc[w][n16*2+1], a0,a1,a2,a3, b2,b3);
                }
            }
        }

        if (t < 11) store_x((t+1)&1);
        __syncthreads();
        if (t < 10){
            issue_w((t+2)*64, t&1);
            stage_x((t+2)*64);
        }
    }

    const int r = m0 + wm*16 + (lane >> 2);
    const int c = (lane & 3)*2;
    #pragma unroll
    for (int w=0; w<3; w++){
        const float* bias = (w==0)?bq:((w==1)?bk:bv);
        u16* out = (w==0)?g_qh:((w==1)?g_kh:g_vh);
        const float scale = (w==0)?0.125f:1.0f;
        #pragma unroll
        for (int nb=0; nb<4; nb++){
            int n = wn*32 + nb*8 + c;
            float b0v = bias[n], b1v = bias[n+1];
            *(u32*)&out[(size_t)r*HEAD + n] =
                h2((acc[w][nb][0]+b0v)*scale, (acc[w][nb][1]+b1v)*scale);
            *(u32*)&out[(size_t)(r+8)*HEAD + n] =
                h2((acc[w][nb][2]+b0v)*scale, (acc[w][nb][3]+b1v)*scale);
        }
    }
}

// ============================================================================
// Kernel 2: HMMA flash attention (unchanged from R10-R12 pass).
// ============================================================================
#define AP 72
#define A_Q  0
#define A_K0 (128*AP)
#define A_K1 (2*128*AP)
#define A_V0 (3*128*AP)
#define A_V1 (4*128*AP)
#define ATTN_SMEM (5*128*AP*2)   // 92160 B

__global__ __launch_bounds__(256, 2) void attn_hmma_kernel()
{
    extern __shared__ u16 smh[];
    const int tid  = threadIdx.x;
    const int warp = tid >> 5;
    const int lane = tid & 31;
    const int b = blockIdx.y, qt = blockIdx.x, z = blockIdx.z;
    const int t0 = z*16;

    const u16* __restrict__ qg = g_qh + ((size_t)b*SEQL + qt*128)*HEAD;
    const u16* __restrict__ kg = g_kh + (size_t)b*SEQL*HEAD;
    const u16* __restrict__ vg = g_vh + (size_t)b*SEQL*HEAD;

    const u32 smb = smem_u32(smh);
    const int l15 = lane & 15;
    const int lhi = ((lane >> 4) & 1) * 8;
    const u32 qbase = smb + (A_Q + (warp*16 + l15)*AP + lhi)*2;
    const u32 kb_[2] = { smb + (A_K0 + l15*AP + lhi)*2, smb + (A_K1 + l15*AP + lhi)*2 };
    const u32 vb_[2] = { smb + (A_V0 + l15*AP + lhi)*2, smb + (A_V1 + l15*AP + lhi)*2 };

    auto issue_kv = [&](int t, int buf){
        u32 kdst = smb + ((buf ? A_K1 : A_K0))*2;
        u32 vdst = smb + ((buf ? A_V1 : A_V0))*2;
        const u16* ks = kg + (size_t)t*128*HEAD;
        const u16* vs = vg + (size_t)t*128*HEAD;
        #pragma unroll
        for (int i=0;i<4;i++){
            int slot = tid + i*256;
            int row = slot >> 3, ch = slot & 7;
            u32 off = (u32)(row*AP + ch*8)*2;
            cp16(kdst + off, ks + row*HEAD + ch*8);
            cp16(vdst + off, vs + row*HEAD + ch*8);
        }
        CP_COMMIT();
    };

    {
        #pragma unroll
        for (int i=0;i<4;i++){
            int slot = tid + i*256;
            int row = slot >> 3, ch = slot & 7;
            cp16(smb + (A_Q + row*AP + ch*8)*2, qg + row*HEAD + ch*8);
        }
        u32 kdst = smb + A_K0*2, vdst = smb + A_V0*2;
        const u16* ks = kg + (size_t)t0*128*HEAD;
        const u16* vs = vg + (size_t)t0*128*HEAD;
        #pragma unroll
        for (int i=0;i<4;i++){
            int slot = tid + i*256;
            int row = slot >> 3, ch = slot & 7;
            u32 off = (u32)(row*AP + ch*8)*2;
            cp16(kdst + off, ks + row*HEAD + ch*8);
            cp16(vdst + off, vs + row*HEAD + ch*8);
        }
        CP_COMMIT();
        issue_kv(t0+1, 1);
    }

    float oacc[8][4];
    #pragma unroll
    for (int i=0;i<8;i++)
        #pragma unroll
        for (int j=0;j<4;j++) oacc[i][j] = 0.f;
    float lsum0 = 0.f, lsum1 = 0.f;
    u32 qf[4][4];
    bool qloaded = false;

    for (int t = 0; t < 16; t++){
        if (t < 15) CP_WAIT1(); else CP_WAIT0();
        __syncthreads();

        if (!qloaded){
            #pragma unroll
            for (int kb=0; kb<4; kb++)
                ldsm_x4(qf[kb][0], qf[kb][1], qf[kb][2], qf[kb][3], qbase + kb*32);
            qloaded = true;
        }

        const u32 kbb = kb_[t&1];
        const u32 vbb = vb_[t&1];

        #pragma unroll
        for (int h=0; h<4; h++){
            float sacc[4][4];
            #pragma unroll
            for (int i=0;i<4;i++)
                #pragma unroll
                for (int j=0;j<4;j++) sacc[i][j] = 0.f;

            #pragma unroll
            for (int kb=0; kb<4; kb++){
                #pragma unroll
                for (int e=0; e<2; e++){
                    u32 b0,b1,b2,b3;
                    ldsm_x4(b0,b1,b2,b3, kbb + ((h*32 + e*16)*AP)*2 + kb*32);
                    mma_f16(sacc[2*e  ], qf[kb][0],qf[kb][1],qf[kb][2],qf[kb][3], b0,b2);
                    mma_f16(sacc[2*e+1], qf[kb][0],qf[kb][1],qf[kb][2],qf[kb][3], b1,b3);
                }
            }

            u32 pa[2][4];
            #pragma unroll
            for (int nb=0; nb<4; nb++){
                float p0 = __expf(sacc[nb][0]);
                float p1 = __expf(sacc[nb][1]);
                float p2 = __expf(sacc[nb][2]);
                float p3 = __expf(sacc[nb][3]);
                lsum0 += p0 + p1;
                lsum1 += p2 + p3;
                pa[nb>>1][(nb&1)*2 + 0] = h2(p0, p1);
                pa[nb>>1][(nb&1)*2 + 1] = h2(p2, p3);
            }

            #pragma unroll
            for (int j=0; j<2; j++){
                int kc = h*2 + j;
                #pragma unroll
                for (int np=0; np<4; np++){
                    u32 b0,b1,b2,b3;
                    ldsm_x4t(b0,b1,b2,b3, vbb + (kc*16*AP)*2 + np*32);
                    mma_f16(oacc[np*2  ], pa[j][0],pa[j][1],pa[j][2],pa[j][3], b0,b1);
                    mma_f16(oacc[np*2+1], pa[j][0],pa[j][1],pa[j][2],pa[j][3], b2,b3);
                }
            }
        }
        __syncthreads();
        if (t + 2 < 16) issue_kv(t0 + t + 2, t&1);
    }

    lsum0 += __shfl_xor_sync(0xffffffffu, lsum0, 1);
    lsum0 += __shfl_xor_sync(0xffffffffu, lsum0, 2);
    lsum1 += __shfl_xor_sync(0xffffffffu, lsum1, 1);
    lsum1 += __shfl_xor_sync(0xffffffffu, lsum1, 2);

    float* og = (z ? g_o1 : g_o0) + ((size_t)b*SEQL + qt*128)*HEAD;
    float* lg = (z ? g_l1 : g_l0) + (size_t)b*SEQL + qt*128;
    const int r = warp*16 + (lane >> 2);
    const int c = (lane & 3)*2;
    if ((lane & 3) == 0){
        lg[r]   = lsum0;
        lg[r+8] = lsum1;
    }
    #pragma unroll
    for (int nb=0; nb<8; nb++){
        *(float2*)&og[(size_t)r*HEAD + nb*8 + c] =
            make_float2(oacc[nb][0], oacc[nb][1]);
        *(float2*)&og[(size_t)(r+8)*HEAD + nb*8 + c] =
            make_float2(oacc[nb][2], oacc[nb][3]);
    }
}

// ============================================================================
// Kernel 2b: combine halves, normalize, emit ctx as PLAIN f16. 8 elems/thr.
// ============================================================================
__global__ void ctxcomb_kernel()
{
    int slot = blockIdx.x*256 + threadIdx.x;   // 131072 slots x 8 elems
    int e = slot*8;
    int row = e >> 6;
    float inv = 1.0f / (g_l0[row] + g_l1[row]);
    uint4 hv;
    {
        float4 o0 = *(const float4*)&g_o0[e];
        float4 o1 = *(const float4*)&g_o1[e];
        hv.x = h2((o0.x+o1.x)*inv, (o0.y+o1.y)*inv);
        hv.y = h2((o0.z+o1.z)*inv, (o0.w+o1.w)*inv);
    }
    {
        float4 o0 = *(const float4*)&g_o0[e+4];
        float4 o1 = *(const float4*)&g_o1[e+4];
        hv.z = h2((o0.x+o1.x)*inv, (o0.y+o1.y)*inv);
        hv.w = h2((o0.z+o1.z)*inv, (o0.w+o1.w)*inv);
    }
    *(uint4*)&g_ctxh[e] = hv;
}

// ============================================================================
// Kernel 3: output projection, SINGLE-PASS f16, 1536 light CTAs.
// grid (128 m, 12 n), 256 thr = 8 warps x 16 rows. Static smem 27.6 KB.
// ============================================================================
#define CP 72
#define OP 72

__global__ __launch_bounds__(256) void oproj_hmma(
    const float* __restrict__ bo,
    float* __restrict__ out)
{
    __shared__ u16 cs[128*CP];
    __shared__ u16 ws[64*OP];

    const int tid  = threadIdx.x;
    const int warp = tid >> 5;
    const int lane = tid & 31;
    const int m0 = blockIdx.x * 128;
    const int n0 = blockIdx.y * 64;
    const u32 smc = smem_u32(cs);
    const u32 smw = smem_u32(ws);

    // ctx tile: 128 rows x 8 chunks = 1024 (4/thread)
    #pragma unroll
    for (int i=0;i<4;i++){
        int slot = tid + i*256;
        int row = slot >> 3, ch = slot & 7;
        cp16(smc + (u32)(row*CP + ch*8)*2, &g_ctxh[(size_t)(m0+row)*HEAD + ch*8]);
    }
    // Wo tile: 64 rows x 8 chunks = 512 (2/thread)
    #pragma unroll
    for (int i=0;i<2;i++){
        int slot = tid + i*256;
        int row = slot >> 3, ch = slot & 7;
        cp16(smw + (u32)(row*OP + ch*8)*2, &g_wo[(size_t)row*HIDDEN + n0 + ch*8]);
    }
    CP_COMMIT();
    CP_WAIT0();
    __syncthreads();

    const int l15 = lane & 15;
    const int lhi = ((lane >> 4) & 1) * 8;
    const u32 abase = smc + ((warp*16 + l15)*CP + lhi)*2;
    const u32 bbase = smw + (l15*OP + lhi)*2;

    u32 af[4][4];
    #pragma unroll
    for (int kb=0; kb<4; kb++)
        ldsm_x4(af[kb][0], af[kb][1], af[kb][2], af[kb][3], abase + kb*32);

    float acc[8][4];
    #pragma unroll
    for (int i=0;i<8;i++)
        #pragma unroll
        for (int j=0;j<4;j++) acc[i][j] = 0.f;

    #pragma unroll
    for (int kb=0; kb<4; kb++){
        #pragma unroll
        for (int n16=0; n16<4; n16++){
            u32 b0,b1,b2,b3;
            ldsm_x4t(b0,b1,b2,b3, bbase + (kb*16*OP)*2 + n16*32);
            mma_f16(acc[n16*2  ], af[kb][0],af[kb][1],af[kb][2],af[kb][3], b0,b1);
            mma_f16(acc[n16*2+1], af[kb][0],af[kb][1],af[kb][2],af[kb][3], b2,b3);
        }
    }

    const int r = m0 + warp*16 + (lane >> 2);
    const int c = (lane & 3)*2;
    #pragma unroll
    for (int nb=0; nb<8; nb++){
        int n = n0 + nb*8 + c;
        float b0v = bo[n], b1v = bo[n+1];
        *(float2*)&out[(size_t)r*HIDDEN + n] =
            make_float2(acc[nb][0]+b0v, acc[nb][1]+b1v);
        *(float2*)&out[(size_t)(r+8)*HIDDEN + n] =
            make_float2(acc[nb][2]+b0v, acc[nb][3]+b1v);
    }
}

extern "C" void kernel_launch(void* const* d_in, const int* in_sizes, int n_in,
                              void* d_out, int out_size)
{
    const float* x  = (const float*)d_in[0];
    const float* Wq = (const float*)d_in[1];
    const float* bq = (const float*)d_in[2];
    const float* Wk = (const float*)d_in[3];
    const float* bk = (const float*)d_in[4];
    const float* Wv = (const float*)d_in[5];
    const float* bv = (const float*)d_in[6];
    const float* Wo = (const float*)d_in[7];
    const float* bo = (const float*)d_in[8];
    float* out = (float*)d_out;

    cudaFuncSetAttribute(qkv_hmma,         cudaFuncAttributeMaxDynamicSharedMemorySize, QKV_SMEM);
    cudaFuncSetAttribute(attn_hmma_kernel, cudaFuncAttributeMaxDynamicSharedMemorySize, ATTN_SMEM);

    wcvt_kernel<<<384, 256>>>(Wq, Wk, Wv, Wo);
    qkv_hmma<<<256, 256, QKV_SMEM>>>(x, bq, bk, bv);
    attn_hmma_kernel<<<dim3(32,4,2), 256, ATTN_SMEM>>>();
    ctxcomb_kernel<<<512, 256>>>();
    oproj_hmma<<<dim3(128,12), 256>>>(bo, out);
}